// round 5
// baseline (speedup 1.0000x reference)
#include <cuda_runtime.h>
#include <cuda_bf16.h>

#define EPS 1e-6f
#define NB 16
#define NA 10
#define NT 30
#define NP_POLY 16
#define NV 200
#define SEGP (NV - 1)                 // 199 segs per poly
#define NSEG (NP_POLY * SEGP)         // 3184 segs per batch
#define NPTS 300                      // points per batch
#define CHUNK 128                     // segs per block (4 exact warp strides)
#define NCHUNK ((NSEG + CHUNK - 1) / CHUNK)   // 25
#define GRID (NB * NCHUNK)            // 400
#define NPTS_WARP 8
#define WARPS 8
#define THREADS (WARPS * 32)          // 256
#define PASSES ((NPTS + WARPS*NPTS_WARP - 1) / (WARPS*NPTS_WARP))  // 5
#define NSLOT (NB * NPTS)             // 4800

__device__ unsigned g_md[NSLOT];      // max of ~bits(d2)  -> min d2
__device__ int      g_ct[NSLOT];      // crossing counts
__device__ unsigned g_counter = 0;

__global__ __launch_bounds__(THREADS)
void offroad_kernel(const float* __restrict__ points,
                    const float* __restrict__ polys,
                    float* __restrict__ out) {
    __shared__ float4 s4[CHUNK];
    __shared__ float2 s2[CHUNK];
    __shared__ int s_isLast;

    int b = blockIdx.x / NCHUNK;
    int c = blockIdx.x - b * NCHUNK;
    int seg0 = c * CHUNK;
    int nseg = min(CHUNK, NSEG - seg0);

    int tid = threadIdx.x;

    if (tid < nseg) {
        int g = seg0 + tid;
        int p = g / SEGP;
        int j = g - p * SEGP;
        const float2* pv = (const float2*)polys + ((size_t)(b * NP_POLY + p)) * NV + j;
        float2 v0 = pv[0];
        float2 v1 = pv[1];
        float evx = v1.x - v0.x;
        float evy = v1.y - v0.y;
        float esq = fmaf(evx, evx, evy * evy);
        float rcp_esq = 1.0f / (esq + EPS);      // exact IEEE, matches reference
        float slope   = evy / (evx + EPS);
        float rcp_sl  = 1.0f / (slope + EPS);
        s4[tid] = make_float4(v0.x, v0.y, v1.x, v1.y);
        s2[tid] = make_float2(rcp_esq, rcp_sl);
    }
    __syncthreads();

    int wid = tid >> 5;
    int ln  = tid & 31;
    const float2* pts2 = (const float2*)points + (size_t)b * NPTS;

#pragma unroll 1
    for (int pass = 0; pass < PASSES; pass++) {
        int pbase = pass * (WARPS * NPTS_WARP) + wid * NPTS_WARP;
        if (pbase >= NPTS) continue;   // no barriers inside this loop

        float px[NPTS_WARP], py[NPTS_WARP], md[NPTS_WARP];
        int   ct[NPTS_WARP];
#pragma unroll
        for (int k = 0; k < NPTS_WARP; k++) {
            int pidx = pbase + k;
            float2 pt = (pidx < NPTS) ? pts2[pidx] : make_float2(1e30f, 1e30f);
            px[k] = pt.x; py[k] = pt.y;
            md[k] = 3.4e38f;
            ct[k] = 0;
        }

        for (int s = ln; s < nseg; s += 32) {
            float4 sg = s4[s];
            float2 rr = s2[s];
            float evx = sg.z - sg.x;
            float evy = sg.w - sg.y;
#pragma unroll
            for (int k = 0; k < NPTS_WARP; k++) {
                float v1x = px[k] - sg.x;
                float v1y = py[k] - sg.y;
                float dot = fmaf(v1x, evx, v1y * evy);
                float proj = __saturatef(dot * rr.x);
                float dx = fmaf(-evx, proj, v1x);
                float dy = fmaf(-evy, proj, v1y);
                float d2 = fmaf(dx, dx, dy * dy);
                md[k] = fminf(md[k], d2);
                bool c1 = (sg.y <= py[k]);
                bool c2 = (sg.w <= py[k]);
                float ix = fmaf(v1y, rr.y, sg.x);
                ct[k] += ((c1 != c2) & (ix > px[k])) ? 1 : 0;
            }
        }

#pragma unroll
        for (int k = 0; k < NPTS_WARP; k++) {
#pragma unroll
            for (int o = 16; o > 0; o >>= 1) {
                md[k] = fminf(md[k], __shfl_xor_sync(0xffffffffu, md[k], o));
                ct[k] += __shfl_xor_sync(0xffffffffu, ct[k], o);
            }
        }
        if (ln == 0) {
#pragma unroll
            for (int k = 0; k < NPTS_WARP; k++) {
                int pidx = pbase + k;
                if (pidx < NPTS) {
                    int idx = b * NPTS + pidx;
                    atomicMax(&g_md[idx], ~__float_as_uint(md[k]));
                    if (ct[k]) atomicAdd(&g_ct[idx], ct[k]);
                }
            }
        }
    }

    // ---- last-block finisher ----
    __threadfence();
    __syncthreads();
    if (tid == 0) {
        unsigned old = atomicAdd(&g_counter, 1u);
        s_isLast = (old == (unsigned)(GRID - 1));
        if (s_isLast) g_counter = 0;
    }
    __syncthreads();

    if (s_isLast) {
        __threadfence();
        if (tid < NB * NA) {
            int base = tid * NT;       // == b*300 + a*30
            float sum = 0.0f;
#pragma unroll
            for (int t = 0; t < NT; t++) {
                float m = __uint_as_float(~g_md[base + t]);
                int cc = g_ct[base + t];
                float d = sqrtf(fmaxf(m, EPS));
                if (cc & 1) d = -d;
                sum += fmaxf(d + 0.5f, 0.0f);
            }
            out[tid] = sum;
        }
        __syncthreads();
        for (int i = tid; i < NSLOT; i += THREADS) {
            g_md[i] = 0u;
            g_ct[i] = 0;
        }
    }
}

extern "C" void kernel_launch(void* const* d_in, const int* in_sizes, int n_in,
                              void* d_out, int out_size) {
    const float* points = (const float*)d_in[0];  // (16,10,30,2)
    const float* polys  = (const float*)d_in[1];  // (16,16,200,2)
    float* out = (float*)d_out;                   // (16,10)
    offroad_kernel<<<GRID, THREADS>>>(points, polys, out);
}

// round 6
// speedup vs baseline: 1.0088x; 1.0088x over previous
#include <cuda_runtime.h>
#include <cuda_bf16.h>

#define EPS 1e-6f
#define NB 16
#define NA 10
#define NT 30
#define NP_POLY 16
#define NV 200
#define SEGP (NV - 1)                 // 199 real segs per poly
#define SEGPAD 224                    // padded to 7 * 32
#define NITER (SEGPAD / 32)           // 7 full warp strides
#define NPTS_WARP 8
#define WARPS 4
#define THREADS (WARPS * 32)          // 128
#define NBA (NB * NA)                 // 160
#define GRID (NBA * NP_POLY)          // 2560
#define NSLOT (NBA * NT)              // 4800

// padded per-(batch,poly) segment tables
__device__ float4 g_seg4[NB * NP_POLY * SEGPAD];  // {sx, sy, ex, ey}
__device__ float2 g_seg2[NB * NP_POLY * SEGPAD];  // {1/(esq+eps), 1/(slope+eps)}

// folded partials per (ba, t); zero-init valid for ~bits atomicMax scheme
__device__ unsigned g_md[NSLOT];      // max over ~bits(d2)  == min d2
__device__ int      g_ct[NSLOT];
__device__ unsigned g_counter = 0;

__device__ __forceinline__ unsigned warp_redux_min_u32(unsigned v) {
    unsigned r;
    asm("redux.sync.min.u32 %0, %1, 0xffffffff;" : "=r"(r) : "r"(v));
    return r;
}
__device__ __forceinline__ int warp_redux_add_s32(int v) {
    int r;
    asm("redux.sync.add.s32 %0, %1, 0xffffffff;" : "=r"(r) : "r"(v));
    return r;
}

__global__ void precompute_kernel(const float* __restrict__ polys) {
    int idx = blockIdx.x * blockDim.x + threadIdx.x;
    if (idx >= NB * NP_POLY * SEGPAD) return;
    int bp = idx / SEGPAD;
    int j  = idx - bp * SEGPAD;
    if (j < SEGP) {
        const float2* pv = (const float2*)polys + (size_t)bp * NV + j;
        float2 v0 = pv[0];
        float2 v1 = pv[1];
        float evx = v1.x - v0.x;
        float evy = v1.y - v0.y;
        float esq = fmaf(evx, evx, evy * evy);
        float rcp_esq = 1.0f / (esq + EPS);      // exact IEEE, matches reference
        float slope   = evy / (evx + EPS);
        float rcp_sl  = 1.0f / (slope + EPS);
        g_seg4[idx] = make_float4(v0.x, v0.y, v1.x, v1.y);
        g_seg2[idx] = make_float2(rcp_esq, rcp_sl);
    } else {
        // inert dummy: cond_y false (1e30<=py never), d2 -> inf (never min)
        g_seg4[idx] = make_float4(1e30f, 1e30f, 1e30f, 1e30f);
        g_seg2[idx] = make_float2(0.0f, 0.0f);
    }
}

__global__ __launch_bounds__(THREADS)
void offroad_main_kernel(const float* __restrict__ points,
                         float* __restrict__ out) {
    __shared__ int s_isLast;

    int bx = blockIdx.x;
    int p  = bx & (NP_POLY - 1);
    int ba = bx >> 4;                  // b*NA + a
    int b  = ba / NA;

    int wid = threadIdx.x >> 5;
    int ln  = threadIdx.x & 31;
    int t0  = wid * NPTS_WARP;

    float px[NPTS_WARP], py[NPTS_WARP], md[NPTS_WARP];
    int   ct[NPTS_WARP];

    const float2* pts2 = (const float2*)points;
#pragma unroll
    for (int k = 0; k < NPTS_WARP; k++) {
        int t = t0 + k;
        float2 pt = (t < NT) ? pts2[ba * NT + t] : make_float2(1e30f, 1e30f);
        px[k] = pt.x; py[k] = pt.y;
        md[k] = 3.4e38f;
        ct[k] = 0;
    }

    const float4* s4 = g_seg4 + ((size_t)(b * NP_POLY + p)) * SEGPAD;
    const float2* s2 = g_seg2 + ((size_t)(b * NP_POLY + p)) * SEGPAD;

#pragma unroll
    for (int i = 0; i < NITER; i++) {
        int s = ln + i * 32;
        float4 sg = __ldg(&s4[s]);
        float2 rr = __ldg(&s2[s]);
        float evx = sg.z - sg.x;
        float evy = sg.w - sg.y;
#pragma unroll
        for (int k = 0; k < NPTS_WARP; k++) {
            float v1x = px[k] - sg.x;
            float v1y = py[k] - sg.y;
            float dot = fmaf(v1x, evx, v1y * evy);
            float proj = __saturatef(dot * rr.x);
            float dx = fmaf(-evx, proj, v1x);
            float dy = fmaf(-evy, proj, v1y);
            float d2 = fmaf(dx, dx, dy * dy);
            md[k] = fminf(md[k], d2);
            bool c1 = (sg.y <= py[k]);
            bool c2 = (sg.w <= py[k]);
            float ix = fmaf(v1y, rr.y, sg.x);
            ct[k] += ((c1 != c2) & (ix > px[k])) ? 1 : 0;
        }
    }

    // per-point warp fold via redux, then fold across blocks via L2 atomics
#pragma unroll
    for (int k = 0; k < NPTS_WARP; k++) {
        unsigned mb = warp_redux_min_u32(__float_as_uint(md[k]));  // d2 >= 0
        int      cc = warp_redux_add_s32(ct[k]);
        int t = t0 + k;
        if (ln == 0 && t < NT) {
            int idx = ba * NT + t;
            atomicMax(&g_md[idx], ~mb);
            if (cc) atomicAdd(&g_ct[idx], cc);
        }
    }

    // ---- last-block finisher ----
    __threadfence();
    __syncthreads();
    if (threadIdx.x == 0) {
        unsigned old = atomicAdd(&g_counter, 1u);
        s_isLast = (old == (unsigned)(GRID - 1));
        if (s_isLast) g_counter = 0;
    }
    __syncthreads();

    if (s_isLast) {
        __threadfence();
        for (int o = threadIdx.x; o < NBA; o += THREADS) {
            int base = o * NT;
            float sum = 0.0f;
#pragma unroll
            for (int t = 0; t < NT; t++) {
                float m = __uint_as_float(~g_md[base + t]);
                int cc = g_ct[base + t];
                float d = sqrtf(fmaxf(m, EPS));
                if (cc & 1) d = -d;
                sum += fmaxf(d + 0.5f, 0.0f);
            }
            out[o] = sum;
        }
        __syncthreads();
        // reset for next graph replay
        for (int i = threadIdx.x; i < NSLOT; i += THREADS) {
            g_md[i] = 0u;
            g_ct[i] = 0;
        }
    }
}

extern "C" void kernel_launch(void* const* d_in, const int* in_sizes, int n_in,
                              void* d_out, int out_size) {
    const float* points = (const float*)d_in[0];  // (16,10,30,2)
    const float* polys  = (const float*)d_in[1];  // (16,16,200,2)
    float* out = (float*)d_out;                   // (16,10)

    int total = NB * NP_POLY * SEGPAD;
    precompute_kernel<<<(total + 255) / 256, 256>>>(polys);
    offroad_main_kernel<<<GRID, THREADS>>>(points, out);
}